// round 4
// baseline (speedup 1.0000x reference)
#include <cuda_runtime.h>
#include <math_constants.h>

// Problem constants
#define BB   16
#define DD   1024
#define TT   4096
#define CDIM 8
#define CSZ  1024

#define NTHREADS 256
#define TPB      256               // t-columns per block
#define TILES_PER_B (TT / TPB)     // 16
#define GRID (BB * TILES_PER_B)    // 256

// Output layout (concatenated float32):
// out [B,D,T], commitment_loss [B], codebook_loss [B], indices [B,T], z_e [B,CD,T]
#define OFF_CL  (BB * DD * TT)
#define OFF_CB  (OFF_CL + BB)
#define OFF_IDX (OFF_CB + BB)
#define OFF_ZE  (OFF_IDX + BB * TT)

__device__ float g_losspart[GRID];

// ---------------- f32x2 packed helpers ----------------
typedef unsigned long long u64;

__device__ __forceinline__ u64 pk(float lo, float hi) {
    u64 r; asm("mov.b64 %0, {%1, %2};" : "=l"(r) : "f"(lo), "f"(hi)); return r;
}
__device__ __forceinline__ void upk(float& lo, float& hi, u64 v) {
    asm("mov.b64 {%0, %1}, %2;" : "=f"(lo), "=f"(hi) : "l"(v));
}
__device__ __forceinline__ u64 f2(u64 a, u64 b, u64 c) {
    u64 d; asm("fma.rn.f32x2 %0, %1, %2, %3;" : "=l"(d) : "l"(a), "l"(b), "l"(c)); return d;
}

// Dynamic smem layout (floats):
//   s_winT  [0      , 8192)   : in-proj weight transposed [d][k]        32 KB
//   s_cbn2  [8192   , 16384)  : normalized codebook pair-interleaved    32 KB
//                               [(c/2)][k][c&1]
//   s_wout2 [16384  , 24576)  : out-proj weight pair-interleaved        32 KB
//                               [(d/2)][k][d&1]
//   s_bias  [24576  , 25600)  : out-proj bias [d]                        4 KB
//   s_scale [25600  , 25608)  : in-proj row scales
//   s_red   [25608  , 25616)  : loss partials per warp
#define SM_WINT  0
#define SM_CBN2  8192
#define SM_WOUT2 16384
#define SM_BIAS  24576
#define SM_SCALE 25600
#define SM_RED   25608
#define SM_FLOATS 25616

// ---------------------------------------------------------------------------
// Mega kernel: builds all tables in smem, then each thread owns one t-column
// with NO inter-phase syncs (warps desynchronize -> DRAM never idles).
// ---------------------------------------------------------------------------
__global__ void __launch_bounds__(NTHREADS, 2)
vq_mega(const float* __restrict__ z,
        const float* __restrict__ ipv, const float* __restrict__ ipg,
        const float* __restrict__ in_b,
        const float* __restrict__ opv, const float* __restrict__ opg,
        const float* __restrict__ out_b,
        const float* __restrict__ cb,
        float* __restrict__ out) {
    extern __shared__ __align__(16) float sm[];
    float* s_winT  = sm + SM_WINT;
    float* s_cbn2  = sm + SM_CBN2;
    float* s_wout2 = sm + SM_WOUT2;
    float* s_bias  = sm + SM_BIAS;
    float* s_scale = sm + SM_SCALE;
    float* s_red   = sm + SM_RED;

    const int tid = threadIdx.x;
    const int wid = tid >> 5;
    const int lid = tid & 31;

    // ===== build tables =====
    // in-proj row norms: warp o reduces row o (1024 floats = 256 float4)
    if (wid < CDIM) {
        const float4* row = (const float4*)(ipv + wid * DD);
        float s = 0.f;
#pragma unroll
        for (int j = 0; j < 8; j++) {
            float4 v = __ldg(row + lid + 32 * j);
            s = fmaf(v.x, v.x, fmaf(v.y, v.y, fmaf(v.z, v.z, fmaf(v.w, v.w, s))));
        }
#pragma unroll
        for (int off = 16; off > 0; off >>= 1)
            s += __shfl_down_sync(0xffffffffu, s, off);
        if (lid == 0) s_scale[wid] = __ldg(ipg + wid) / sqrtf(s);
    }
    __syncthreads();
    // in-proj transpose-store
    for (int idx = tid; idx < CDIM * DD; idx += NTHREADS) {
        int o = idx >> 10;
        int d = idx & (DD - 1);
        s_winT[d * CDIM + o] = __ldg(ipv + idx) * s_scale[o];
    }
    // codebook: l2-normalize, pair-interleave
    for (int c = tid; c < CSZ; c += NTHREADS) {
        const float4* r = (const float4*)(cb + c * CDIM);
        float4 a = __ldg(r), b4 = __ldg(r + 1);
        float s = a.x * a.x + a.y * a.y + a.z * a.z + a.w * a.w
                + b4.x * b4.x + b4.y * b4.y + b4.z * b4.z + b4.w * b4.w;
        float inv = 1.f / fmaxf(sqrtf(s), 1e-12f);
        float* dst = s_cbn2 + (c >> 1) * 16 + (c & 1);
        dst[0] = a.x * inv;  dst[2] = a.y * inv;  dst[4]  = a.z * inv;  dst[6]  = a.w * inv;
        dst[8] = b4.x * inv; dst[10] = b4.y * inv; dst[12] = b4.z * inv; dst[14] = b4.w * inv;
    }
    // out-proj: weight-norm rows, pair-interleave; bias
    for (int d = tid; d < DD; d += NTHREADS) {
        const float4* r = (const float4*)(opv + d * CDIM);
        float4 a = __ldg(r), b4 = __ldg(r + 1);
        float s = a.x * a.x + a.y * a.y + a.z * a.z + a.w * a.w
                + b4.x * b4.x + b4.y * b4.y + b4.z * b4.z + b4.w * b4.w;
        float sc = __ldg(opg + d) / sqrtf(s);
        float* dst = s_wout2 + (d >> 1) * 16 + (d & 1);
        dst[0] = a.x * sc;  dst[2] = a.y * sc;  dst[4]  = a.z * sc;  dst[6]  = a.w * sc;
        dst[8] = b4.x * sc; dst[10] = b4.y * sc; dst[12] = b4.z * sc; dst[14] = b4.w * sc;
        s_bias[d] = __ldg(out_b + d);
    }
    __syncthreads();

    // ===== per-thread column work (no more block syncs until loss) =====
    const int b    = blockIdx.x >> 4;
    const int tile = blockIdx.x & (TILES_PER_B - 1);
    const int t    = tile * TPB + tid;

    // ---- phase 1: z_e = winT^T . z[:,t] + bias ----
    u64 a01 = 0, a23 = 0, a45 = 0, a67 = 0;
    {
        const float* zp = z + (size_t)b * (DD * TT) + t;
#pragma unroll 8
        for (int d = 0; d < DD; d++) {
            float zv = __ldg(zp + (size_t)d * TT);
            u64 zz = pk(zv, zv);
            const ulonglong2* w = (const ulonglong2*)(s_winT + d * CDIM);
            ulonglong2 w0 = w[0];
            ulonglong2 w1 = w[1];
            a01 = f2(w0.x, zz, a01);
            a23 = f2(w0.y, zz, a23);
            a45 = f2(w1.x, zz, a45);
            a67 = f2(w1.y, zz, a67);
        }
    }
    float ze[CDIM];
    upk(ze[0], ze[1], a01);
    upk(ze[2], ze[3], a23);
    upk(ze[4], ze[5], a45);
    upk(ze[6], ze[7], a67);
#pragma unroll
    for (int k = 0; k < CDIM; k++) ze[k] += __ldg(in_b + k);

    // write z_e [B, CD, T]
    {
        float* zeo = out + OFF_ZE + (size_t)b * (CDIM * TT) + t;
#pragma unroll
        for (int k = 0; k < CDIM; k++) zeo[(size_t)k * TT] = ze[k];
    }

    // ---- phase 2: argmax over 1024 codes (2 codes per iter) ----
    float best = -CUDART_INF_F;
    int bi = 0;
    {
        u64 zd[CDIM];
#pragma unroll
        for (int k = 0; k < CDIM; k++) zd[k] = pk(ze[k], ze[k]);
#pragma unroll 4
        for (int p = 0; p < CSZ / 2; p++) {
            const ulonglong2* r = (const ulonglong2*)(s_cbn2 + p * 16);
            ulonglong2 r0 = r[0], r1 = r[1], r2 = r[2], r3 = r[3];
            u64 dd = 0;
            dd = f2(r0.x, zd[0], dd);
            dd = f2(r0.y, zd[1], dd);
            dd = f2(r1.x, zd[2], dd);
            dd = f2(r1.y, zd[3], dd);
            dd = f2(r2.x, zd[4], dd);
            dd = f2(r2.y, zd[5], dd);
            dd = f2(r3.x, zd[6], dd);
            dd = f2(r3.y, zd[7], dd);
            float d0, d1;
            upk(d0, d1, dd);
            int c0 = 2 * p;
            if (d0 > best) { best = d0; bi = c0; }     // strict >: first max wins
            if (d1 > best) { best = d1; bi = c0 + 1; }
        }
    }
    out[OFF_IDX + (size_t)b * TT + t] = (float)bi;

    // gather raw codebook row (L1/L2 resident)
    float zq[CDIM];
    {
        const float4* cb4 = (const float4*)cb;
        float4 q0 = __ldg(cb4 + 2 * bi);
        float4 q1 = __ldg(cb4 + 2 * bi + 1);
        zq[0] = q0.x; zq[1] = q0.y; zq[2] = q0.z; zq[3] = q0.w;
        zq[4] = q1.x; zq[5] = q1.y; zq[6] = q1.z; zq[7] = q1.w;
    }

    // loss scalar for this column (commitment == codebook numerically)
    float ls = 0.f;
#pragma unroll
    for (int k = 0; k < CDIM; k++) {
        float d = ze[k] - zq[k];
        ls = fmaf(d, d, ls);
    }

    // ---- phase 3: out[:,t] = wout . z_q + bias (2 d-rows per iter) ----
    {
        u64 zq2[CDIM];
#pragma unroll
        for (int k = 0; k < CDIM; k++) zq2[k] = pk(zq[k], zq[k]);
        float* op = out + (size_t)b * (DD * TT) + t;
#pragma unroll 4
        for (int p = 0; p < DD / 2; p++) {
            const ulonglong2* r = (const ulonglong2*)(s_wout2 + p * 16);
            ulonglong2 r0 = r[0], r1 = r[1], r2 = r[2], r3 = r[3];
            float2 bv = *(const float2*)(s_bias + 2 * p);
            u64 acc = pk(bv.x, bv.y);
            acc = f2(r0.x, zq2[0], acc);
            acc = f2(r0.y, zq2[1], acc);
            acc = f2(r1.x, zq2[2], acc);
            acc = f2(r1.y, zq2[3], acc);
            acc = f2(r2.x, zq2[4], acc);
            acc = f2(r2.y, zq2[5], acc);
            acc = f2(r3.x, zq2[6], acc);
            acc = f2(r3.y, zq2[7], acc);
            float v0, v1;
            upk(v0, v1, acc);
            op[(size_t)(2 * p) * TT]     = v0;
            op[(size_t)(2 * p + 1) * TT] = v1;
        }
    }

    // ---- block loss reduction (deterministic) ----
#pragma unroll
    for (int off = 16; off > 0; off >>= 1)
        ls += __shfl_down_sync(0xffffffffu, ls, off);
    if (lid == 0) s_red[wid] = ls;
    __syncthreads();
    if (tid == 0) {
        float tot = 0.f;
#pragma unroll
        for (int w = 0; w < NTHREADS / 32; w++) tot += s_red[w];
        g_losspart[blockIdx.x] = tot;
    }
}

// ---------------------------------------------------------------------------
// Finish: deterministic fixed-order loss reduction.
// ---------------------------------------------------------------------------
__global__ void vq_finish(float* __restrict__ out) {
    int b = threadIdx.x;
    if (b < BB) {
        float s = 0.f;
        for (int i = 0; i < TILES_PER_B; i++) s += g_losspart[b * TILES_PER_B + i];
        s *= (1.0f / (float)(CDIM * TT));
        out[OFF_CL + b] = s;
        out[OFF_CB + b] = s;
    }
}

extern "C" void kernel_launch(void* const* d_in, const int* in_sizes, int n_in,
                              void* d_out, int out_size) {
    const float* z   = (const float*)d_in[0];
    const float* ipv = (const float*)d_in[1];
    const float* ipg = (const float*)d_in[2];
    const float* ipb = (const float*)d_in[3];
    const float* opv = (const float*)d_in[4];
    const float* opg = (const float*)d_in[5];
    const float* opb = (const float*)d_in[6];
    const float* cb  = (const float*)d_in[7];
    float* out = (float*)d_out;

    const int smem_bytes = SM_FLOATS * sizeof(float);   // ~100 KB
    cudaFuncSetAttribute(vq_mega, cudaFuncAttributeMaxDynamicSharedMemorySize, smem_bytes);

    vq_mega<<<GRID, NTHREADS, smem_bytes>>>(z, ipv, ipg, ipb, opv, opg, opb, cb, out);
    vq_finish<<<1, 32>>>(out);
}